// round 12
// baseline (speedup 1.0000x reference)
#include <cuda_runtime.h>
#include <cuda_bf16.h>
#include <mma.h>
#include <cstdint>

using namespace nvcuda;

#define NN 256
#define MATS (256LL * 256 * 256)

// scratch (static __device__ arrays: allocation-free)
__device__ __nv_bfloat16 g_Phi[MATS], g_Plo[MATS];
__device__ __nv_bfloat16 g_P2hi[MATS], g_P2lo[MATS];
__device__ __nv_bfloat16 g_P3hi[MATS], g_P3lo[MATS];
__device__ __nv_bfloat16 g_P4hi[MATS], g_P4lo[MATS];

__device__ __forceinline__ uint32_t smem_u32(const void* p) {
    uint32_t a;
    asm("{ .reg .u64 t; cvta.to.shared.u64 t, %1; cvt.u32.u64 %0, t; }" : "=r"(a) : "l"(p));
    return a;
}
__device__ __forceinline__ void cpa16(uint32_t dst, const void* src) {
    asm volatile("cp.async.cg.shared.global [%0], [%1], 16;" :: "r"(dst), "l"(src));
}
__device__ __forceinline__ void cpa_commit() {
    asm volatile("cp.async.commit_group;" ::: "memory");
}
__device__ __forceinline__ float bf2f(__nv_bfloat16 v) { return __bfloat162float(v); }

// ---------------------------------------------------------------------------
// prep: threshold + row-normalize. Warp per row. Writes bf16 hi/lo of P +
// slots 0/1.
// ---------------------------------------------------------------------------
__global__ void __launch_bounds__(256) prep_kernel(const float* __restrict__ A,
                                                   __nv_bfloat16* __restrict__ Phi,
                                                   __nv_bfloat16* __restrict__ Plo,
                                                   float* __restrict__ out)
{
    int row = blockIdx.x * 8 + (threadIdx.x >> 5);
    int lane = threadIdx.x & 31;
    int n = row & 255;

    const float* arow = A + (size_t)row * NN + lane * 8;
    float4 v0 = *(const float4*)(arow);
    float4 v1 = *(const float4*)(arow + 4);
    float f[8] = {v0.x, v0.y, v0.z, v0.w, v1.x, v1.y, v1.z, v1.w};
    float s = 0.0f;
    #pragma unroll
    for (int q = 0; q < 8; q++) {
        f[q] = (f[q] > 0.3f) ? f[q] : 0.0f;
        s += f[q];
    }
    #pragma unroll
    for (int o = 16; o; o >>= 1) s += __shfl_xor_sync(0xffffffffu, s, o);
    float dinv = (s > 0.0f) ? (1.0f / s) : 0.0f;

    uint32_t hp[4], lp[4];
    float p[8];
    #pragma unroll
    for (int q = 0; q < 4; q++) {
        p[2*q]   = f[2*q]   * dinv;
        p[2*q+1] = f[2*q+1] * dinv;
        __nv_bfloat16 h0 = __float2bfloat16_rn(p[2*q]);
        __nv_bfloat16 h1 = __float2bfloat16_rn(p[2*q+1]);
        __nv_bfloat162 hh; hh.x = h0; hh.y = h1;
        hp[q] = *(uint32_t*)&hh;
        __nv_bfloat162 ll;
        ll.x = __float2bfloat16_rn(p[2*q]   - bf2f(h0));
        ll.y = __float2bfloat16_rn(p[2*q+1] - bf2f(h1));
        lp[q] = *(uint32_t*)&ll;
    }
    size_t idx = (size_t)row * NN + lane * 8;
    *(uint4*)(Phi + idx) = make_uint4(hp[0], hp[1], hp[2], hp[3]);
    *(uint4*)(Plo + idx) = make_uint4(lp[0], lp[1], lp[2], lp[3]);

    if (lane == (n >> 3)) out[(size_t)row * 8 + 1] = p[n & 7];
    if (lane == 0)        out[(size_t)row * 8 + 0] = 1.0f;
}

// ---------------------------------------------------------------------------
// WMMA bf16-split GEMM: C = X * Y, row-major [M,K]x[K,N].
// CTA: 256 thr / 8 warps, tile 128x64, warp tile 32x32 (4M x 2N),
// K-chunk 32, 2-stage cp.async pipeline, 3 CTAs/SM.
// Split products: XhYh + XhYl + XlYh (phased loads to cap live registers).
// Epilogue: smem-staged C -> bf16 hi/lo + diag slot.
// blockIdx.z selects one of two problem descriptors (dual launch).
// ---------------------------------------------------------------------------
#define XLD 40
#define YLD 72
#define XARR_B (128 * XLD * 2)               // 10240
#define YARR_B (32 * YLD * 2)                // 4608
#define OFF_XL XARR_B                        // 10240
#define OFF_YH (2 * XARR_B)                  // 20480
#define OFF_YL (2 * XARR_B + YARR_B)         // 25088
#define STAGE_B (2 * XARR_B + 2 * YARR_B)    // 29696
#define GEMM_SMEM (2 * STAGE_B)              // 59392 (3 CTA/SM: 178176)
#define CLD 68                               // C stage: 128*68*4 = 34816 fits

__global__ void __launch_bounds__(256, 3)
gemm_wmma(const __nv_bfloat16* __restrict__ Xh0, const __nv_bfloat16* __restrict__ Xl0,
          const __nv_bfloat16* __restrict__ Yh0, const __nv_bfloat16* __restrict__ Yl0,
          __nv_bfloat16* __restrict__ Chi0, __nv_bfloat16* __restrict__ Clo0, int slot0,
          const __nv_bfloat16* __restrict__ Xh1, const __nv_bfloat16* __restrict__ Xl1,
          const __nv_bfloat16* __restrict__ Yh1, const __nv_bfloat16* __restrict__ Yl1,
          __nv_bfloat16* __restrict__ Chi1, __nv_bfloat16* __restrict__ Clo1, int slot1,
          float* __restrict__ out)
{
    const __nv_bfloat16* Xh = blockIdx.z ? Xh1 : Xh0;
    const __nv_bfloat16* Xl = blockIdx.z ? Xl1 : Xl0;
    const __nv_bfloat16* Yh = blockIdx.z ? Yh1 : Yh0;
    const __nv_bfloat16* Yl = blockIdx.z ? Yl1 : Yl0;
    __nv_bfloat16* Chi = blockIdx.z ? Chi1 : Chi0;
    __nv_bfloat16* Clo = blockIdx.z ? Clo1 : Clo0;
    int slot = blockIdx.z ? slot1 : slot0;

    int b = blockIdx.y;
    size_t base = (size_t)b << 16;
    Xh += base; Xl += base; Yh += base; Yl += base;
    Chi += base; Clo += base;
    int tileM = (blockIdx.x >> 2) << 7;       // 0,128
    int tileN = (blockIdx.x & 3) << 6;        // 0,64,128,192

    extern __shared__ __align__(128) char sm[];
    uint32_t smb = smem_u32(sm);

    int t = threadIdx.x;
    int w = t >> 5, wm = w & 3, wn = w >> 2;  // warp tile rows wm*32, cols wn*32

    int xr = t >> 1, xq = t & 1;   // X: 128 rows x 2x32B per array
    int yr = t >> 3, yq = t & 7;   // Y: 32 rows x 8x16B per array

    wmma::fragment<wmma::accumulator, 16, 16, 16, float> acc[2][2];
    #pragma unroll
    for (int i = 0; i < 2; i++)
        #pragma unroll
        for (int j = 0; j < 2; j++) wmma::fill_fragment(acc[i][j], 0.0f);

    auto issue = [&](int kc, int s) {
        int k0 = kc << 5;
        uint32_t sb = smb + s * STAGE_B;
        {
            const __nv_bfloat16* gh = Xh + (size_t)(tileM + xr) * NN + k0 + xq * 16;
            const __nv_bfloat16* gl = Xl + (size_t)(tileM + xr) * NN + k0 + xq * 16;
            uint32_t d = sb + xr * (XLD * 2) + xq * 32;
            cpa16(d, gh);               cpa16(d + 16, gh + 8);
            cpa16(d + OFF_XL, gl);      cpa16(d + OFF_XL + 16, gl + 8);
        }
        {
            const __nv_bfloat16* gh = Yh + (size_t)(k0 + yr) * NN + tileN + yq * 8;
            const __nv_bfloat16* gl = Yl + (size_t)(k0 + yr) * NN + tileN + yq * 8;
            uint32_t d = sb + OFF_YH + yr * (YLD * 2) + yq * 16;
            cpa16(d, gh);
            cpa16(d + YARR_B, gl);
        }
        cpa_commit();
    };

    issue(0, 0);

    #pragma unroll 1
    for (int kc = 0; kc < 8; kc++) {
        int s = kc & 1;
        asm volatile("cp.async.wait_group 0;" ::: "memory");
        __syncthreads();
        if (kc < 7) issue(kc + 1, s ^ 1);

        const char* sb = sm + s * STAGE_B;
        const __nv_bfloat16* bXh = (const __nv_bfloat16*)(sb);
        const __nv_bfloat16* bXl = (const __nv_bfloat16*)(sb + OFF_XL);
        const __nv_bfloat16* bYh = (const __nv_bfloat16*)(sb + OFF_YH);
        const __nv_bfloat16* bYl = (const __nv_bfloat16*)(sb + OFF_YL);

        #pragma unroll
        for (int kk = 0; kk < 2; kk++) {
            int ks = kk * 16;
            wmma::fragment<wmma::matrix_a, 16, 16, 16, __nv_bfloat16, wmma::row_major> af[2];
            wmma::fragment<wmma::matrix_b, 16, 16, 16, __nv_bfloat16, wmma::row_major> bh[2], bl[2];
            // phase 1: Xh * (Yh, Yl)
            #pragma unroll
            for (int i = 0; i < 2; i++)
                wmma::load_matrix_sync(af[i], bXh + (wm * 32 + i * 16) * XLD + ks, XLD);
            #pragma unroll
            for (int j = 0; j < 2; j++) {
                wmma::load_matrix_sync(bh[j], bYh + ks * YLD + wn * 32 + j * 16, YLD);
                wmma::load_matrix_sync(bl[j], bYl + ks * YLD + wn * 32 + j * 16, YLD);
            }
            #pragma unroll
            for (int i = 0; i < 2; i++)
                #pragma unroll
                for (int j = 0; j < 2; j++) {
                    wmma::mma_sync(acc[i][j], af[i], bh[j], acc[i][j]);
                    wmma::mma_sync(acc[i][j], af[i], bl[j], acc[i][j]);
                }
            // phase 2: Xl * Yh (reuse af registers)
            #pragma unroll
            for (int i = 0; i < 2; i++)
                wmma::load_matrix_sync(af[i], bXl + (wm * 32 + i * 16) * XLD + ks, XLD);
            #pragma unroll
            for (int i = 0; i < 2; i++)
                #pragma unroll
                for (int j = 0; j < 2; j++)
                    wmma::mma_sync(acc[i][j], af[i], bh[j], acc[i][j]);
        }
    }

    // epilogue: stage 128x64 fp32 tile in smem, emit bf16 hi/lo + diag slot
    __syncthreads();
    float* cs = (float*)sm;
    #pragma unroll
    for (int i = 0; i < 2; i++)
        #pragma unroll
        for (int j = 0; j < 2; j++)
            wmma::store_matrix_sync(cs + (wm * 32 + i * 16) * CLD + wn * 32 + j * 16,
                                    acc[i][j], CLD, wmma::mem_row_major);
    __syncthreads();

    if ((tileM >> 7) == (tileN >> 7) && t < 64) {
        int gr = tileN + t;
        out[((size_t)(b << 8) + gr) * 8 + slot] = cs[(gr - tileM + t - t + (tileN - tileM) + t) * 0 + (tileN - tileM + t) * CLD + t];
    }

    #pragma unroll
    for (int it = 0; it < 4; it++) {
        int idx = t + it * 256;          // 1024 chunks of 8 floats
        int r = idx >> 3;                // 128 rows
        int c = (idx & 7) << 3;          // 8 chunks x 8 floats
        const float* sp = cs + r * CLD + c;
        float f[8];
        #pragma unroll
        for (int q = 0; q < 8; q++) f[q] = sp[q];
        uint32_t hp[4], lp[4];
        #pragma unroll
        for (int q = 0; q < 4; q++) {
            __nv_bfloat16 h0 = __float2bfloat16_rn(f[2*q]);
            __nv_bfloat16 h1 = __float2bfloat16_rn(f[2*q+1]);
            __nv_bfloat162 hh; hh.x = h0; hh.y = h1;
            hp[q] = *(uint32_t*)&hh;
            __nv_bfloat162 ll;
            ll.x = __float2bfloat16_rn(f[2*q]   - bf2f(h0));
            ll.y = __float2bfloat16_rn(f[2*q+1] - bf2f(h1));
            lp[q] = *(uint32_t*)&ll;
        }
        *(uint4*)(Chi + (size_t)(tileM + r) * NN + tileN + c) = make_uint4(hp[0], hp[1], hp[2], hp[3]);
        *(uint4*)(Clo + (size_t)(tileM + r) * NN + tileN + c) = make_uint4(lp[0], lp[1], lp[2], lp[3]);
    }
}

// ---------------------------------------------------------------------------
// diag3: d5 = <P2[i,:], P3[:,i]>, d6 = <P3[i,:], P3[:,i]>,
//        d7 = <P3[i,:], P4[:,i]>. Columns staged through smem (coalesced),
//        all inputs bf16 hi/lo reconstructed.
// ---------------------------------------------------------------------------
__global__ void __launch_bounds__(256) diag3_kernel(const __nv_bfloat16* __restrict__ P2h,
                                                    const __nv_bfloat16* __restrict__ P2l,
                                                    const __nv_bfloat16* __restrict__ P3h,
                                                    const __nv_bfloat16* __restrict__ P3l,
                                                    const __nv_bfloat16* __restrict__ P4h,
                                                    const __nv_bfloat16* __restrict__ P4l,
                                                    float* __restrict__ out)
{
    __shared__ float c3[32][33], c4[32][33];
    int b = blockIdx.x >> 3;
    int i0 = (blockIdx.x & 7) << 5;
    size_t base = (size_t)b << 16;
    int t = threadIdx.x;
    int il = t >> 3, jq = t & 7;
    int lc = t & 31, lr = t >> 5;

    const __nv_bfloat16* r2h = P2h + base + (size_t)(i0 + il) * NN;
    const __nv_bfloat16* r2l = P2l + base + (size_t)(i0 + il) * NN;
    const __nv_bfloat16* r3h = P3h + base + (size_t)(i0 + il) * NN;
    const __nv_bfloat16* r3l = P3l + base + (size_t)(i0 + il) * NN;

    float a5 = 0.f, a6 = 0.f, a7 = 0.f;
    #pragma unroll 1
    for (int jt = 0; jt < 8; jt++) {
        int j0 = jt << 5;
        #pragma unroll
        for (int qq = 0; qq < 4; qq++) {
            int jl = lr + qq * 8;
            size_t src = base + (size_t)(j0 + jl) * NN + i0 + lc;
            c3[jl][lc] = bf2f(P3h[src]) + bf2f(P3l[src]);
            c4[jl][lc] = bf2f(P4h[src]) + bf2f(P4l[src]);
        }
        __syncthreads();

        uint2 u2h = *(const uint2*)(r2h + j0 + jq * 4);
        uint2 u2l = *(const uint2*)(r2l + j0 + jq * 4);
        uint2 u3h = *(const uint2*)(r3h + j0 + jq * 4);
        uint2 u3l = *(const uint2*)(r3l + j0 + jq * 4);
        float x2[4], x3[4];
        {
            __nv_bfloat162 h0 = *(__nv_bfloat162*)&u2h.x, h1 = *(__nv_bfloat162*)&u2h.y;
            __nv_bfloat162 l0 = *(__nv_bfloat162*)&u2l.x, l1 = *(__nv_bfloat162*)&u2l.y;
            x2[0] = bf2f(h0.x) + bf2f(l0.x); x2[1] = bf2f(h0.y) + bf2f(l0.y);
            x2[2] = bf2f(h1.x) + bf2f(l1.x); x2[3] = bf2f(h1.y) + bf2f(l1.y);
        }
        {
            __nv_bfloat162 h0 = *(__nv_bfloat162*)&u3h.x, h1 = *(__nv_bfloat162*)&u3h.y;
            __nv_bfloat162 l0 = *(__nv_bfloat162*)&u3l.x, l1 = *(__nv_bfloat162*)&u3l.y;
            x3[0] = bf2f(h0.x) + bf2f(l0.x); x3[1] = bf2f(h0.y) + bf2f(l0.y);
            x3[2] = bf2f(h1.x) + bf2f(l1.x); x3[3] = bf2f(h1.y) + bf2f(l1.y);
        }
        int jb = jq * 4;
        #pragma unroll
        for (int k = 0; k < 4; k++) {
            float cc3 = c3[jb + k][il];
            float cc4 = c4[jb + k][il];
            a5 = fmaf(x2[k], cc3, a5);
            a6 = fmaf(x3[k], cc3, a6);
            a7 = fmaf(x3[k], cc4, a7);
        }
        __syncthreads();
    }
    #pragma unroll
    for (int o = 4; o; o >>= 1) {
        a5 += __shfl_down_sync(0xffffffffu, a5, o);
        a6 += __shfl_down_sync(0xffffffffu, a6, o);
        a7 += __shfl_down_sync(0xffffffffu, a7, o);
    }
    if (jq == 0) {
        size_t o = ((size_t)(b << 8) + i0 + il) * 8;
        out[o + 5] = a5;
        out[o + 6] = a6;
        out[o + 7] = a7;
    }
}

// ---------------------------------------------------------------------------
extern "C" void kernel_launch(void* const* d_in, const int* in_sizes, int n_in,
                              void* d_out, int out_size)
{
    const float* A = (const float*)d_in[0];
    float* out = (float*)d_out;

    __nv_bfloat16 *Phi, *Plo, *P2hi, *P2lo, *P3hi, *P3lo, *P4hi, *P4lo;
    cudaGetSymbolAddress((void**)&Phi,  g_Phi);
    cudaGetSymbolAddress((void**)&Plo,  g_Plo);
    cudaGetSymbolAddress((void**)&P2hi, g_P2hi);
    cudaGetSymbolAddress((void**)&P2lo, g_P2lo);
    cudaGetSymbolAddress((void**)&P3hi, g_P3hi);
    cudaGetSymbolAddress((void**)&P3lo, g_P3lo);
    cudaGetSymbolAddress((void**)&P4hi, g_P4hi);
    cudaGetSymbolAddress((void**)&P4lo, g_P4lo);

    cudaFuncSetAttribute(gemm_wmma, cudaFuncAttributeMaxDynamicSharedMemorySize, GEMM_SMEM);

    // 1) P (bf16 hi/lo) + slots 0,1
    prep_kernel<<<8192, 256>>>(A, Phi, Plo, out);
    // 2) P2 = P * P (bf16 hi/lo) + slot 2
    gemm_wmma<<<dim3(8, 256, 1), 256, GEMM_SMEM>>>(
        Phi, Plo, Phi, Plo, P2hi, P2lo, 2,
        Phi, Plo, Phi, Plo, P2hi, P2lo, 2, out);
    // 3) dual launch: P3 = P*P2 (slot 3) and P4 = P2*P2 (slot 4)
    gemm_wmma<<<dim3(8, 256, 2), 256, GEMM_SMEM>>>(
        Phi,  Plo,  P2hi, P2lo, P3hi, P3lo, 3,
        P2hi, P2lo, P2hi, P2lo, P4hi, P4lo, 4, out);
    // 4) slots 5,6,7
    diag3_kernel<<<2048, 256>>>(P2hi, P2lo, P3hi, P3lo, P4hi, P4lo, out);
}

// round 13
// speedup vs baseline: 1.1277x; 1.1277x over previous
#include <cuda_runtime.h>
#include <cuda_bf16.h>
#include <mma.h>
#include <cstdint>

using namespace nvcuda;

#define NN 256
#define MATS (256LL * 256 * 256)

// scratch (static __device__ arrays: allocation-free)
__device__ __nv_bfloat16 g_Phi[MATS], g_Plo[MATS];
__device__ __nv_bfloat16 g_P2hi[MATS], g_P2lo[MATS];
__device__ __nv_bfloat16 g_P3hi[MATS], g_P3lo[MATS];
__device__ __nv_bfloat16 g_P4hi[MATS], g_P4lo[MATS];

__device__ __forceinline__ uint32_t smem_u32(const void* p) {
    uint32_t a;
    asm("{ .reg .u64 t; cvta.to.shared.u64 t, %1; cvt.u32.u64 %0, t; }" : "=r"(a) : "l"(p));
    return a;
}
__device__ __forceinline__ void cpa16(uint32_t dst, const void* src) {
    asm volatile("cp.async.cg.shared.global [%0], [%1], 16;" :: "r"(dst), "l"(src));
}
__device__ __forceinline__ void cpa_commit() {
    asm volatile("cp.async.commit_group;" ::: "memory");
}
__device__ __forceinline__ float bf2f(__nv_bfloat16 v) { return __bfloat162float(v); }

// ---------------------------------------------------------------------------
// prep: threshold + row-normalize. Warp per row. Writes bf16 hi/lo of P +
// slots 0/1.
// ---------------------------------------------------------------------------
__global__ void __launch_bounds__(256) prep_kernel(const float* __restrict__ A,
                                                   __nv_bfloat16* __restrict__ Phi,
                                                   __nv_bfloat16* __restrict__ Plo,
                                                   float* __restrict__ out)
{
    int row = blockIdx.x * 8 + (threadIdx.x >> 5);
    int lane = threadIdx.x & 31;
    int n = row & 255;

    const float* arow = A + (size_t)row * NN + lane * 8;
    float4 v0 = *(const float4*)(arow);
    float4 v1 = *(const float4*)(arow + 4);
    float f[8] = {v0.x, v0.y, v0.z, v0.w, v1.x, v1.y, v1.z, v1.w};
    float s = 0.0f;
    #pragma unroll
    for (int q = 0; q < 8; q++) {
        f[q] = (f[q] > 0.3f) ? f[q] : 0.0f;
        s += f[q];
    }
    #pragma unroll
    for (int o = 16; o; o >>= 1) s += __shfl_xor_sync(0xffffffffu, s, o);
    float dinv = (s > 0.0f) ? (1.0f / s) : 0.0f;

    uint32_t hp[4], lp[4];
    float p[8];
    #pragma unroll
    for (int q = 0; q < 4; q++) {
        p[2*q]   = f[2*q]   * dinv;
        p[2*q+1] = f[2*q+1] * dinv;
        __nv_bfloat16 h0 = __float2bfloat16_rn(p[2*q]);
        __nv_bfloat16 h1 = __float2bfloat16_rn(p[2*q+1]);
        __nv_bfloat162 hh; hh.x = h0; hh.y = h1;
        hp[q] = *(uint32_t*)&hh;
        __nv_bfloat162 ll;
        ll.x = __float2bfloat16_rn(p[2*q]   - bf2f(h0));
        ll.y = __float2bfloat16_rn(p[2*q+1] - bf2f(h1));
        lp[q] = *(uint32_t*)&ll;
    }
    size_t idx = (size_t)row * NN + lane * 8;
    *(uint4*)(Phi + idx) = make_uint4(hp[0], hp[1], hp[2], hp[3]);
    *(uint4*)(Plo + idx) = make_uint4(lp[0], lp[1], lp[2], lp[3]);

    if (lane == (n >> 3)) out[(size_t)row * 8 + 1] = p[n & 7];
    if (lane == 0)        out[(size_t)row * 8 + 0] = 1.0f;
}

// ---------------------------------------------------------------------------
// WMMA bf16-split GEMM (R8-proven): C = X * Y, row-major [M,K]x[K,N].
// CTA: 256 thr / 8 warps, tile 128x128, warp tile 64x32, K-chunk 32,
// THREE-stage cp.async pipeline (depth 2), single sync per chunk.
// 3 split products: XhYh + XhYl + XlYh.
// Epilogue: smem-staged C -> bf16 hi/lo + diag slot.
// blockIdx.z selects one of two problem descriptors (dual launch).
// ---------------------------------------------------------------------------
#define XLD 40
#define YLD 136
#define XARR_B (128 * XLD * 2)               // 10240
#define YARR_B (32 * YLD * 2)                // 8704
#define OFF_XL XARR_B
#define OFF_YH (2 * XARR_B)
#define OFF_YL (2 * XARR_B + YARR_B)
#define STAGE_B (2 * XARR_B + 2 * YARR_B)    // 37888
#define GEMM_SMEM (3 * STAGE_B)              // 113664 (2 CTA/SM)
#define CLD 132                              // epilogue stage ld; 128*132*4=67584 fits

__global__ void __launch_bounds__(256, 2)
gemm_wmma(const __nv_bfloat16* __restrict__ Xh0, const __nv_bfloat16* __restrict__ Xl0,
          const __nv_bfloat16* __restrict__ Yh0, const __nv_bfloat16* __restrict__ Yl0,
          __nv_bfloat16* __restrict__ Chi0, __nv_bfloat16* __restrict__ Clo0, int slot0,
          const __nv_bfloat16* __restrict__ Xh1, const __nv_bfloat16* __restrict__ Xl1,
          const __nv_bfloat16* __restrict__ Yh1, const __nv_bfloat16* __restrict__ Yl1,
          __nv_bfloat16* __restrict__ Chi1, __nv_bfloat16* __restrict__ Clo1, int slot1,
          float* __restrict__ out)
{
    const __nv_bfloat16* Xh = blockIdx.z ? Xh1 : Xh0;
    const __nv_bfloat16* Xl = blockIdx.z ? Xl1 : Xl0;
    const __nv_bfloat16* Yh = blockIdx.z ? Yh1 : Yh0;
    const __nv_bfloat16* Yl = blockIdx.z ? Yl1 : Yl0;
    __nv_bfloat16* Chi = blockIdx.z ? Chi1 : Chi0;
    __nv_bfloat16* Clo = blockIdx.z ? Clo1 : Clo0;
    int slot = blockIdx.z ? slot1 : slot0;

    int b = blockIdx.y;
    size_t base = (size_t)b << 16;
    Xh += base; Xl += base; Yh += base; Yl += base;
    Chi += base; Clo += base;
    int tileM = (blockIdx.x >> 1) << 7;
    int tileN = (blockIdx.x & 1) << 7;

    extern __shared__ __align__(128) char sm[];
    uint32_t smb = smem_u32(sm);

    int t = threadIdx.x;
    int w = t >> 5, wm = w & 1, wn = w >> 1;

    int xr = t >> 1, xq = t & 1;   // X: 128 rows x 2x32B
    int yr = t >> 4, yq = t & 15;  // Y: 32 rows x 16x16B

    wmma::fragment<wmma::accumulator, 16, 16, 16, float> acc[4][2];
    #pragma unroll
    for (int i = 0; i < 4; i++)
        #pragma unroll
        for (int j = 0; j < 2; j++) wmma::fill_fragment(acc[i][j], 0.0f);

    auto issue = [&](int kc, int s) {
        int k0 = kc << 5;
        uint32_t sb = smb + s * STAGE_B;
        {
            const __nv_bfloat16* gh = Xh + (size_t)(tileM + xr) * NN + k0 + xq * 16;
            const __nv_bfloat16* gl = Xl + (size_t)(tileM + xr) * NN + k0 + xq * 16;
            uint32_t d = sb + xr * (XLD * 2) + xq * 32;
            cpa16(d, gh);               cpa16(d + 16, gh + 8);
            cpa16(d + OFF_XL, gl);      cpa16(d + OFF_XL + 16, gl + 8);
        }
        {
            const __nv_bfloat16* gh = Yh + (size_t)(k0 + yr) * NN + tileN + yq * 8;
            const __nv_bfloat16* gl = Yl + (size_t)(k0 + yr) * NN + tileN + yq * 8;
            uint32_t d = sb + OFF_YH + yr * (YLD * 2) + yq * 16;
            cpa16(d, gh);               cpa16(d + 16 * (YLD * 2), gh + 16 * NN);
            cpa16(d + YARR_B, gl);      cpa16(d + YARR_B + 16 * (YLD * 2), gl + 16 * NN);
        }
        cpa_commit();
    };

    issue(0, 0);
    issue(1, 1);

    int scur = 0, sis = 2;
    #pragma unroll 1
    for (int kc = 0; kc < 8; kc++) {
        if (kc < 6) asm volatile("cp.async.wait_group 1;" ::: "memory");
        else        asm volatile("cp.async.wait_group 0;" ::: "memory");
        __syncthreads();
        if (kc < 6) issue(kc + 2, sis);

        const char* sb = sm + scur * STAGE_B;
        const __nv_bfloat16* bXh = (const __nv_bfloat16*)(sb);
        const __nv_bfloat16* bXl = (const __nv_bfloat16*)(sb + OFF_XL);
        const __nv_bfloat16* bYh = (const __nv_bfloat16*)(sb + OFF_YH);
        const __nv_bfloat16* bYl = (const __nv_bfloat16*)(sb + OFF_YL);

        #pragma unroll
        for (int kk = 0; kk < 2; kk++) {
            int ks = kk * 16;
            wmma::fragment<wmma::matrix_a, 16, 16, 16, __nv_bfloat16, wmma::row_major> ah[4], al[4];
            wmma::fragment<wmma::matrix_b, 16, 16, 16, __nv_bfloat16, wmma::row_major> bh[2], bl[2];
            #pragma unroll
            for (int i = 0; i < 4; i++) {
                wmma::load_matrix_sync(ah[i], bXh + (wm * 64 + i * 16) * XLD + ks, XLD);
                wmma::load_matrix_sync(al[i], bXl + (wm * 64 + i * 16) * XLD + ks, XLD);
            }
            #pragma unroll
            for (int j = 0; j < 2; j++) {
                wmma::load_matrix_sync(bh[j], bYh + ks * YLD + wn * 32 + j * 16, YLD);
                wmma::load_matrix_sync(bl[j], bYl + ks * YLD + wn * 32 + j * 16, YLD);
            }
            #pragma unroll
            for (int i = 0; i < 4; i++)
                #pragma unroll
                for (int j = 0; j < 2; j++) {
                    wmma::mma_sync(acc[i][j], ah[i], bh[j], acc[i][j]);
                    wmma::mma_sync(acc[i][j], ah[i], bl[j], acc[i][j]);
                    wmma::mma_sync(acc[i][j], al[i], bh[j], acc[i][j]);
                }
        }
        scur = (scur == 2) ? 0 : scur + 1;
        sis  = (sis  == 2) ? 0 : sis + 1;
        __syncthreads();
    }

    // epilogue: stage 128x128 fp32 tile in smem, emit bf16 hi/lo + diag slot
    float* cs = (float*)sm;
    #pragma unroll
    for (int i = 0; i < 4; i++)
        #pragma unroll
        for (int j = 0; j < 2; j++)
            wmma::store_matrix_sync(cs + (wm * 64 + i * 16) * CLD + wn * 32 + j * 16,
                                    acc[i][j], CLD, wmma::mem_row_major);
    __syncthreads();

    if (tileM == tileN && t < 128)
        out[((size_t)(b << 8) + tileM + t) * 8 + slot] = cs[t * CLD + t];

    #pragma unroll
    for (int it = 0; it < 8; it++) {
        int idx = t + it * 256;
        int r = idx >> 4;
        int c = (idx & 15) << 3;
        const float* sp = cs + r * CLD + c;
        float f[8];
        #pragma unroll
        for (int q = 0; q < 8; q++) f[q] = sp[q];
        uint32_t hp[4], lp[4];
        #pragma unroll
        for (int q = 0; q < 4; q++) {
            __nv_bfloat16 h0 = __float2bfloat16_rn(f[2*q]);
            __nv_bfloat16 h1 = __float2bfloat16_rn(f[2*q+1]);
            __nv_bfloat162 hh; hh.x = h0; hh.y = h1;
            hp[q] = *(uint32_t*)&hh;
            __nv_bfloat162 ll;
            ll.x = __float2bfloat16_rn(f[2*q]   - bf2f(h0));
            ll.y = __float2bfloat16_rn(f[2*q+1] - bf2f(h1));
            lp[q] = *(uint32_t*)&ll;
        }
        *(uint4*)(Chi + (size_t)(tileM + r) * NN + tileN + c) = make_uint4(hp[0], hp[1], hp[2], hp[3]);
        *(uint4*)(Clo + (size_t)(tileM + r) * NN + tileN + c) = make_uint4(lp[0], lp[1], lp[2], lp[3]);
    }
}

// ---------------------------------------------------------------------------
// diag3 v2: ONE barrier, deep MLP.
// Stage full 256x32 column panels of P3 and P4 (reconstructed fp32) in
// dynamic smem, then each thread runs a fully-unrolled dot over j.
// d5 = <P2[i,:], P3[:,i]>, d6 = <P3[i,:], P3[:,i]>, d7 = <P3[i,:], P4[:,i]>
// ---------------------------------------------------------------------------
#define D3_LD   33
#define D3_SMEM (2 * 256 * D3_LD * 4)        // 67584

__global__ void __launch_bounds__(256) diag3_kernel(const __nv_bfloat16* __restrict__ P2h,
                                                    const __nv_bfloat16* __restrict__ P2l,
                                                    const __nv_bfloat16* __restrict__ P3h,
                                                    const __nv_bfloat16* __restrict__ P3l,
                                                    const __nv_bfloat16* __restrict__ P4h,
                                                    const __nv_bfloat16* __restrict__ P4l,
                                                    float* __restrict__ out)
{
    extern __shared__ float dsm[];
    float* c3 = dsm;                    // [256][D3_LD]
    float* c4 = dsm + 256 * D3_LD;

    int b = blockIdx.x >> 3;
    int i0 = (blockIdx.x & 7) << 5;
    size_t base = (size_t)b << 16;
    int t = threadIdx.x;
    int lc = t & 31, lr = t >> 5;       // loader: column lc, rows lr + 8k

    // stage: 32 rows per thread, coalesced 64B per warp per array
    #pragma unroll
    for (int k = 0; k < 32; k++) {
        int j = lr + k * 8;
        size_t src = base + (size_t)j * NN + i0 + lc;
        c3[j * D3_LD + lc] = bf2f(P3h[src]) + bf2f(P3l[src]);
        c4[j * D3_LD + lc] = bf2f(P4h[src]) + bf2f(P4l[src]);
    }
    __syncthreads();

    // dot: thread (il = t>>3, jq = t&7); j chunks of 4 at (jq + 8k)*4
    int il = t >> 3, jq = t & 7;
    const __nv_bfloat16* r2h = P2h + base + (size_t)(i0 + il) * NN;
    const __nv_bfloat16* r2l = P2l + base + (size_t)(i0 + il) * NN;
    const __nv_bfloat16* r3h = P3h + base + (size_t)(i0 + il) * NN;
    const __nv_bfloat16* r3l = P3l + base + (size_t)(i0 + il) * NN;

    float a5 = 0.f, a6 = 0.f, a7 = 0.f;
    #pragma unroll
    for (int k = 0; k < 8; k++) {
        int j0 = (jq + k * 8) * 4;
        uint2 u2h = *(const uint2*)(r2h + j0);
        uint2 u2l = *(const uint2*)(r2l + j0);
        uint2 u3h = *(const uint2*)(r3h + j0);
        uint2 u3l = *(const uint2*)(r3l + j0);
        float x2[4], x3[4];
        {
            __nv_bfloat162 h0 = *(__nv_bfloat162*)&u2h.x, h1 = *(__nv_bfloat162*)&u2h.y;
            __nv_bfloat162 l0 = *(__nv_bfloat162*)&u2l.x, l1 = *(__nv_bfloat162*)&u2l.y;
            x2[0] = bf2f(h0.x) + bf2f(l0.x); x2[1] = bf2f(h0.y) + bf2f(l0.y);
            x2[2] = bf2f(h1.x) + bf2f(l1.x); x2[3] = bf2f(h1.y) + bf2f(l1.y);
        }
        {
            __nv_bfloat162 h0 = *(__nv_bfloat162*)&u3h.x, h1 = *(__nv_bfloat162*)&u3h.y;
            __nv_bfloat162 l0 = *(__nv_bfloat162*)&u3l.x, l1 = *(__nv_bfloat162*)&u3l.y;
            x3[0] = bf2f(h0.x) + bf2f(l0.x); x3[1] = bf2f(h0.y) + bf2f(l0.y);
            x3[2] = bf2f(h1.x) + bf2f(l1.x); x3[3] = bf2f(h1.y) + bf2f(l1.y);
        }
        #pragma unroll
        for (int q = 0; q < 4; q++) {
            float cc3 = c3[(j0 + q) * D3_LD + il];
            float cc4 = c4[(j0 + q) * D3_LD + il];
            a5 = fmaf(x2[q], cc3, a5);
            a6 = fmaf(x3[q], cc3, a6);
            a7 = fmaf(x3[q], cc4, a7);
        }
    }
    #pragma unroll
    for (int o = 4; o; o >>= 1) {
        a5 += __shfl_down_sync(0xffffffffu, a5, o);
        a6 += __shfl_down_sync(0xffffffffu, a6, o);
        a7 += __shfl_down_sync(0xffffffffu, a7, o);
    }
    if (jq == 0) {
        size_t o = ((size_t)(b << 8) + i0 + il) * 8;
        out[o + 5] = a5;
        out[o + 6] = a6;
        out[o + 7] = a7;
    }
}

// ---------------------------------------------------------------------------
extern "C" void kernel_launch(void* const* d_in, const int* in_sizes, int n_in,
                              void* d_out, int out_size)
{
    const float* A = (const float*)d_in[0];
    float* out = (float*)d_out;

    __nv_bfloat16 *Phi, *Plo, *P2hi, *P2lo, *P3hi, *P3lo, *P4hi, *P4lo;
    cudaGetSymbolAddress((void**)&Phi,  g_Phi);
    cudaGetSymbolAddress((void**)&Plo,  g_Plo);
    cudaGetSymbolAddress((void**)&P2hi, g_P2hi);
    cudaGetSymbolAddress((void**)&P2lo, g_P2lo);
    cudaGetSymbolAddress((void**)&P3hi, g_P3hi);
    cudaGetSymbolAddress((void**)&P3lo, g_P3lo);
    cudaGetSymbolAddress((void**)&P4hi, g_P4hi);
    cudaGetSymbolAddress((void**)&P4lo, g_P4lo);

    cudaFuncSetAttribute(gemm_wmma, cudaFuncAttributeMaxDynamicSharedMemorySize, GEMM_SMEM);
    cudaFuncSetAttribute(diag3_kernel, cudaFuncAttributeMaxDynamicSharedMemorySize, D3_SMEM);

    // 1) P (bf16 hi/lo) + slots 0,1
    prep_kernel<<<8192, 256>>>(A, Phi, Plo, out);
    // 2) P2 = P * P (bf16 hi/lo) + slot 2
    gemm_wmma<<<dim3(4, 256, 1), 256, GEMM_SMEM>>>(
        Phi, Plo, Phi, Plo, P2hi, P2lo, 2,
        Phi, Plo, Phi, Plo, P2hi, P2lo, 2, out);
    // 3) dual launch: P3 = P*P2 (slot 3) and P4 = P2*P2 (slot 4)
    gemm_wmma<<<dim3(4, 256, 2), 256, GEMM_SMEM>>>(
        Phi,  Plo,  P2hi, P2lo, P3hi, P3lo, 3,
        P2hi, P2lo, P2hi, P2lo, P4hi, P4lo, 4, out);
    // 4) slots 5,6,7
    diag3_kernel<<<2048, 256, D3_SMEM>>>(P2hi, P2lo, P3hi, P3lo, P4hi, P4lo, out);
}

// round 14
// speedup vs baseline: 1.1463x; 1.0165x over previous
#include <cuda_runtime.h>
#include <cuda_bf16.h>
#include <mma.h>
#include <cstdint>

using namespace nvcuda;

#define NN 256
#define MATS (256LL * 256 * 256)

// scratch (static __device__ arrays: allocation-free)
__device__ __nv_bfloat16 g_Phi[MATS], g_Plo[MATS];
__device__ __nv_bfloat16 g_P2hi[MATS], g_P2lo[MATS];
__device__ __nv_bfloat16 g_P3hi[MATS], g_P3lo[MATS];
__device__ __nv_bfloat16 g_P4hi[MATS], g_P4lo[MATS];

__device__ __forceinline__ uint32_t smem_u32(const void* p) {
    uint32_t a;
    asm("{ .reg .u64 t; cvta.to.shared.u64 t, %1; cvt.u32.u64 %0, t; }" : "=r"(a) : "l"(p));
    return a;
}
__device__ __forceinline__ void cpa16(uint32_t dst, const void* src) {
    asm volatile("cp.async.cg.shared.global [%0], [%1], 16;" :: "r"(dst), "l"(src));
}
__device__ __forceinline__ void cpa_commit() {
    asm volatile("cp.async.commit_group;" ::: "memory");
}
__device__ __forceinline__ float bf2f(__nv_bfloat16 v) { return __bfloat162float(v); }

// ---------------------------------------------------------------------------
// prep: threshold + row-normalize. Warp per row. Writes bf16 hi/lo of P +
// slots 0/1.
// ---------------------------------------------------------------------------
__global__ void __launch_bounds__(256) prep_kernel(const float* __restrict__ A,
                                                   __nv_bfloat16* __restrict__ Phi,
                                                   __nv_bfloat16* __restrict__ Plo,
                                                   float* __restrict__ out)
{
    int row = blockIdx.x * 8 + (threadIdx.x >> 5);
    int lane = threadIdx.x & 31;
    int n = row & 255;

    const float* arow = A + (size_t)row * NN + lane * 8;
    float4 v0 = *(const float4*)(arow);
    float4 v1 = *(const float4*)(arow + 4);
    float f[8] = {v0.x, v0.y, v0.z, v0.w, v1.x, v1.y, v1.z, v1.w};
    float s = 0.0f;
    #pragma unroll
    for (int q = 0; q < 8; q++) {
        f[q] = (f[q] > 0.3f) ? f[q] : 0.0f;
        s += f[q];
    }
    #pragma unroll
    for (int o = 16; o; o >>= 1) s += __shfl_xor_sync(0xffffffffu, s, o);
    float dinv = (s > 0.0f) ? (1.0f / s) : 0.0f;

    uint32_t hp[4], lp[4];
    float p[8];
    #pragma unroll
    for (int q = 0; q < 4; q++) {
        p[2*q]   = f[2*q]   * dinv;
        p[2*q+1] = f[2*q+1] * dinv;
        __nv_bfloat16 h0 = __float2bfloat16_rn(p[2*q]);
        __nv_bfloat16 h1 = __float2bfloat16_rn(p[2*q+1]);
        __nv_bfloat162 hh; hh.x = h0; hh.y = h1;
        hp[q] = *(uint32_t*)&hh;
        __nv_bfloat162 ll;
        ll.x = __float2bfloat16_rn(p[2*q]   - bf2f(h0));
        ll.y = __float2bfloat16_rn(p[2*q+1] - bf2f(h1));
        lp[q] = *(uint32_t*)&ll;
    }
    size_t idx = (size_t)row * NN + lane * 8;
    *(uint4*)(Phi + idx) = make_uint4(hp[0], hp[1], hp[2], hp[3]);
    *(uint4*)(Plo + idx) = make_uint4(lp[0], lp[1], lp[2], lp[3]);

    if (lane == (n >> 3)) out[(size_t)row * 8 + 1] = p[n & 7];
    if (lane == 0)        out[(size_t)row * 8 + 0] = 1.0f;
}

// ---------------------------------------------------------------------------
// WMMA bf16-split GEMM (R8-proven): C = X * Y, row-major [M,K]x[K,N].
// CTA: 256 thr / 8 warps, tile 128x128, warp tile 64x32, K-chunk 32,
// THREE-stage cp.async pipeline (depth 2), single sync per chunk.
// 3 split products: XhYh + XhYl + XlYh.
// Epilogue: smem-staged C -> bf16 hi/lo + diag slot.
// blockIdx.z selects one of two problem descriptors (dual launch).
// ---------------------------------------------------------------------------
#define XLD 40
#define YLD 136
#define XARR_B (128 * XLD * 2)               // 10240
#define YARR_B (32 * YLD * 2)                // 8704
#define OFF_XL XARR_B
#define OFF_YH (2 * XARR_B)
#define OFF_YL (2 * XARR_B + YARR_B)
#define STAGE_B (2 * XARR_B + 2 * YARR_B)    // 37888
#define GEMM_SMEM (3 * STAGE_B)              // 113664 (2 CTA/SM)
#define CLD 132                              // epilogue stage ld; 128*132*4=67584 fits

__global__ void __launch_bounds__(256, 2)
gemm_wmma(const __nv_bfloat16* __restrict__ Xh0, const __nv_bfloat16* __restrict__ Xl0,
          const __nv_bfloat16* __restrict__ Yh0, const __nv_bfloat16* __restrict__ Yl0,
          __nv_bfloat16* __restrict__ Chi0, __nv_bfloat16* __restrict__ Clo0, int slot0,
          const __nv_bfloat16* __restrict__ Xh1, const __nv_bfloat16* __restrict__ Xl1,
          const __nv_bfloat16* __restrict__ Yh1, const __nv_bfloat16* __restrict__ Yl1,
          __nv_bfloat16* __restrict__ Chi1, __nv_bfloat16* __restrict__ Clo1, int slot1,
          float* __restrict__ out)
{
    const __nv_bfloat16* Xh = blockIdx.z ? Xh1 : Xh0;
    const __nv_bfloat16* Xl = blockIdx.z ? Xl1 : Xl0;
    const __nv_bfloat16* Yh = blockIdx.z ? Yh1 : Yh0;
    const __nv_bfloat16* Yl = blockIdx.z ? Yl1 : Yl0;
    __nv_bfloat16* Chi = blockIdx.z ? Chi1 : Chi0;
    __nv_bfloat16* Clo = blockIdx.z ? Clo1 : Clo0;
    int slot = blockIdx.z ? slot1 : slot0;

    int b = blockIdx.y;
    size_t base = (size_t)b << 16;
    Xh += base; Xl += base; Yh += base; Yl += base;
    Chi += base; Clo += base;
    int tileM = (blockIdx.x >> 1) << 7;
    int tileN = (blockIdx.x & 1) << 7;

    extern __shared__ __align__(128) char sm[];
    uint32_t smb = smem_u32(sm);

    int t = threadIdx.x;
    int w = t >> 5, wm = w & 1, wn = w >> 1;

    int xr = t >> 1, xq = t & 1;   // X: 128 rows x 2x32B
    int yr = t >> 4, yq = t & 15;  // Y: 32 rows x 16x16B

    wmma::fragment<wmma::accumulator, 16, 16, 16, float> acc[4][2];
    #pragma unroll
    for (int i = 0; i < 4; i++)
        #pragma unroll
        for (int j = 0; j < 2; j++) wmma::fill_fragment(acc[i][j], 0.0f);

    auto issue = [&](int kc, int s) {
        int k0 = kc << 5;
        uint32_t sb = smb + s * STAGE_B;
        {
            const __nv_bfloat16* gh = Xh + (size_t)(tileM + xr) * NN + k0 + xq * 16;
            const __nv_bfloat16* gl = Xl + (size_t)(tileM + xr) * NN + k0 + xq * 16;
            uint32_t d = sb + xr * (XLD * 2) + xq * 32;
            cpa16(d, gh);               cpa16(d + 16, gh + 8);
            cpa16(d + OFF_XL, gl);      cpa16(d + OFF_XL + 16, gl + 8);
        }
        {
            const __nv_bfloat16* gh = Yh + (size_t)(k0 + yr) * NN + tileN + yq * 8;
            const __nv_bfloat16* gl = Yl + (size_t)(k0 + yr) * NN + tileN + yq * 8;
            uint32_t d = sb + OFF_YH + yr * (YLD * 2) + yq * 16;
            cpa16(d, gh);               cpa16(d + 16 * (YLD * 2), gh + 16 * NN);
            cpa16(d + YARR_B, gl);      cpa16(d + YARR_B + 16 * (YLD * 2), gl + 16 * NN);
        }
        cpa_commit();
    };

    issue(0, 0);
    issue(1, 1);

    int scur = 0, sis = 2;
    #pragma unroll 1
    for (int kc = 0; kc < 8; kc++) {
        if (kc < 6) asm volatile("cp.async.wait_group 1;" ::: "memory");
        else        asm volatile("cp.async.wait_group 0;" ::: "memory");
        __syncthreads();
        if (kc < 6) issue(kc + 2, sis);

        const char* sb = sm + scur * STAGE_B;
        const __nv_bfloat16* bXh = (const __nv_bfloat16*)(sb);
        const __nv_bfloat16* bXl = (const __nv_bfloat16*)(sb + OFF_XL);
        const __nv_bfloat16* bYh = (const __nv_bfloat16*)(sb + OFF_YH);
        const __nv_bfloat16* bYl = (const __nv_bfloat16*)(sb + OFF_YL);

        #pragma unroll
        for (int kk = 0; kk < 2; kk++) {
            int ks = kk * 16;
            wmma::fragment<wmma::matrix_a, 16, 16, 16, __nv_bfloat16, wmma::row_major> ah[4], al[4];
            wmma::fragment<wmma::matrix_b, 16, 16, 16, __nv_bfloat16, wmma::row_major> bh[2], bl[2];
            #pragma unroll
            for (int i = 0; i < 4; i++) {
                wmma::load_matrix_sync(ah[i], bXh + (wm * 64 + i * 16) * XLD + ks, XLD);
                wmma::load_matrix_sync(al[i], bXl + (wm * 64 + i * 16) * XLD + ks, XLD);
            }
            #pragma unroll
            for (int j = 0; j < 2; j++) {
                wmma::load_matrix_sync(bh[j], bYh + ks * YLD + wn * 32 + j * 16, YLD);
                wmma::load_matrix_sync(bl[j], bYl + ks * YLD + wn * 32 + j * 16, YLD);
            }
            #pragma unroll
            for (int i = 0; i < 4; i++)
                #pragma unroll
                for (int j = 0; j < 2; j++) {
                    wmma::mma_sync(acc[i][j], ah[i], bh[j], acc[i][j]);
                    wmma::mma_sync(acc[i][j], ah[i], bl[j], acc[i][j]);
                    wmma::mma_sync(acc[i][j], al[i], bh[j], acc[i][j]);
                }
        }
        scur = (scur == 2) ? 0 : scur + 1;
        sis  = (sis  == 2) ? 0 : sis + 1;
        __syncthreads();
    }

    // epilogue: stage 128x128 fp32 tile in smem, emit bf16 hi/lo + diag slot
    float* cs = (float*)sm;
    #pragma unroll
    for (int i = 0; i < 4; i++)
        #pragma unroll
        for (int j = 0; j < 2; j++)
            wmma::store_matrix_sync(cs + (wm * 64 + i * 16) * CLD + wn * 32 + j * 16,
                                    acc[i][j], CLD, wmma::mem_row_major);
    __syncthreads();

    if (tileM == tileN && t < 128)
        out[((size_t)(b << 8) + tileM + t) * 8 + slot] = cs[t * CLD + t];

    #pragma unroll
    for (int it = 0; it < 8; it++) {
        int idx = t + it * 256;
        int r = idx >> 4;
        int c = (idx & 15) << 3;
        const float* sp = cs + r * CLD + c;
        float f[8];
        #pragma unroll
        for (int q = 0; q < 8; q++) f[q] = sp[q];
        uint32_t hp[4], lp[4];
        #pragma unroll
        for (int q = 0; q < 4; q++) {
            __nv_bfloat16 h0 = __float2bfloat16_rn(f[2*q]);
            __nv_bfloat16 h1 = __float2bfloat16_rn(f[2*q+1]);
            __nv_bfloat162 hh; hh.x = h0; hh.y = h1;
            hp[q] = *(uint32_t*)&hh;
            __nv_bfloat162 ll;
            ll.x = __float2bfloat16_rn(f[2*q]   - bf2f(h0));
            ll.y = __float2bfloat16_rn(f[2*q+1] - bf2f(h1));
            lp[q] = *(uint32_t*)&ll;
        }
        *(uint4*)(Chi + (size_t)(tileM + r) * NN + tileN + c) = make_uint4(hp[0], hp[1], hp[2], hp[3]);
        *(uint4*)(Clo + (size_t)(tileM + r) * NN + tileN + c) = make_uint4(lp[0], lp[1], lp[2], lp[3]);
    }
}

// ---------------------------------------------------------------------------
// diag3 v3: double-buffered 32x33 tiles, ONE sync per j-tile, full occupancy.
// d5 = <P2[i,:], P3[:,i]>, d6 = <P3[i,:], P3[:,i]>, d7 = <P3[i,:], P4[:,i]>
// Iter jt: prefetch tile jt+1 (globals issued before compute), compute from
// buf jt&1, store prefetch into buf^1, single __syncthreads.
// ---------------------------------------------------------------------------
__global__ void __launch_bounds__(256) diag3_kernel(const __nv_bfloat16* __restrict__ P2h,
                                                    const __nv_bfloat16* __restrict__ P2l,
                                                    const __nv_bfloat16* __restrict__ P3h,
                                                    const __nv_bfloat16* __restrict__ P3l,
                                                    const __nv_bfloat16* __restrict__ P4h,
                                                    const __nv_bfloat16* __restrict__ P4l,
                                                    float* __restrict__ out)
{
    __shared__ float c3[2][32][33], c4[2][32][33];   // 16.9 KB
    int b = blockIdx.x >> 3;
    int i0 = (blockIdx.x & 7) << 5;
    size_t base = (size_t)b << 16;
    int t = threadIdx.x;
    int il = t >> 3, jq = t & 7;
    int lc = t & 31, lr = t >> 5;

    const __nv_bfloat16* r2h = P2h + base + (size_t)(i0 + il) * NN;
    const __nv_bfloat16* r2l = P2l + base + (size_t)(i0 + il) * NN;
    const __nv_bfloat16* r3h = P3h + base + (size_t)(i0 + il) * NN;
    const __nv_bfloat16* r3l = P3l + base + (size_t)(i0 + il) * NN;

    // preload tile 0 into buf 0
    #pragma unroll
    for (int qq = 0; qq < 4; qq++) {
        int jl = lr + qq * 8;
        size_t src = base + (size_t)jl * NN + i0 + lc;
        c3[0][jl][lc] = bf2f(P3h[src]) + bf2f(P3l[src]);
        c4[0][jl][lc] = bf2f(P4h[src]) + bf2f(P4l[src]);
    }
    __syncthreads();

    float a5 = 0.f, a6 = 0.f, a7 = 0.f;
    #pragma unroll
    for (int jt = 0; jt < 8; jt++) {
        int buf = jt & 1;
        int j0 = jt << 5;

        // prefetch next tile into registers (globals issue before compute)
        float n3[4], n4[4];
        if (jt < 7) {
            int j0n = (jt + 1) << 5;
            #pragma unroll
            for (int qq = 0; qq < 4; qq++) {
                int jl = lr + qq * 8;
                size_t src = base + (size_t)(j0n + jl) * NN + i0 + lc;
                n3[qq] = bf2f(P3h[src]) + bf2f(P3l[src]);
                n4[qq] = bf2f(P4h[src]) + bf2f(P4l[src]);
            }
        }

        // row segments for this tile
        uint2 u2h = *(const uint2*)(r2h + j0 + jq * 4);
        uint2 u2l = *(const uint2*)(r2l + j0 + jq * 4);
        uint2 u3h = *(const uint2*)(r3h + j0 + jq * 4);
        uint2 u3l = *(const uint2*)(r3l + j0 + jq * 4);
        float x2[4], x3[4];
        {
            __nv_bfloat162 h0 = *(__nv_bfloat162*)&u2h.x, h1 = *(__nv_bfloat162*)&u2h.y;
            __nv_bfloat162 l0 = *(__nv_bfloat162*)&u2l.x, l1 = *(__nv_bfloat162*)&u2l.y;
            x2[0] = bf2f(h0.x) + bf2f(l0.x); x2[1] = bf2f(h0.y) + bf2f(l0.y);
            x2[2] = bf2f(h1.x) + bf2f(l1.x); x2[3] = bf2f(h1.y) + bf2f(l1.y);
        }
        {
            __nv_bfloat162 h0 = *(__nv_bfloat162*)&u3h.x, h1 = *(__nv_bfloat162*)&u3h.y;
            __nv_bfloat162 l0 = *(__nv_bfloat162*)&u3l.x, l1 = *(__nv_bfloat162*)&u3l.y;
            x3[0] = bf2f(h0.x) + bf2f(l0.x); x3[1] = bf2f(h0.y) + bf2f(l0.y);
            x3[2] = bf2f(h1.x) + bf2f(l1.x); x3[3] = bf2f(h1.y) + bf2f(l1.y);
        }

        int jb = jq * 4;
        #pragma unroll
        for (int k = 0; k < 4; k++) {
            float cc3 = c3[buf][jb + k][il];
            float cc4 = c4[buf][jb + k][il];
            a5 = fmaf(x2[k], cc3, a5);
            a6 = fmaf(x3[k], cc3, a6);
            a7 = fmaf(x3[k], cc4, a7);
        }

        // store prefetched tile into the other buffer
        if (jt < 7) {
            #pragma unroll
            for (int qq = 0; qq < 4; qq++) {
                int jl = lr + qq * 8;
                c3[buf ^ 1][jl][lc] = n3[qq];
                c4[buf ^ 1][jl][lc] = n4[qq];
            }
            __syncthreads();
        }
    }
    #pragma unroll
    for (int o = 4; o; o >>= 1) {
        a5 += __shfl_down_sync(0xffffffffu, a5, o);
        a6 += __shfl_down_sync(0xffffffffu, a6, o);
        a7 += __shfl_down_sync(0xffffffffu, a7, o);
    }
    if (jq == 0) {
        size_t o = ((size_t)(b << 8) + i0 + il) * 8;
        out[o + 5] = a5;
        out[o + 6] = a6;
        out[o + 7] = a7;
    }
}

// ---------------------------------------------------------------------------
extern "C" void kernel_launch(void* const* d_in, const int* in_sizes, int n_in,
                              void* d_out, int out_size)
{
    const float* A = (const float*)d_in[0];
    float* out = (float*)d_out;

    __nv_bfloat16 *Phi, *Plo, *P2hi, *P2lo, *P3hi, *P3lo, *P4hi, *P4lo;
    cudaGetSymbolAddress((void**)&Phi,  g_Phi);
    cudaGetSymbolAddress((void**)&Plo,  g_Plo);
    cudaGetSymbolAddress((void**)&P2hi, g_P2hi);
    cudaGetSymbolAddress((void**)&P2lo, g_P2lo);
    cudaGetSymbolAddress((void**)&P3hi, g_P3hi);
    cudaGetSymbolAddress((void**)&P3lo, g_P3lo);
    cudaGetSymbolAddress((void**)&P4hi, g_P4hi);
    cudaGetSymbolAddress((void**)&P4lo, g_P4lo);

    cudaFuncSetAttribute(gemm_wmma, cudaFuncAttributeMaxDynamicSharedMemorySize, GEMM_SMEM);

    // 1) P (bf16 hi/lo) + slots 0,1
    prep_kernel<<<8192, 256>>>(A, Phi, Plo, out);
    // 2) P2 = P * P (bf16 hi/lo) + slot 2
    gemm_wmma<<<dim3(4, 256, 1), 256, GEMM_SMEM>>>(
        Phi, Plo, Phi, Plo, P2hi, P2lo, 2,
        Phi, Plo, Phi, Plo, P2hi, P2lo, 2, out);
    // 3) dual launch: P3 = P*P2 (slot 3) and P4 = P2*P2 (slot 4)
    gemm_wmma<<<dim3(4, 256, 2), 256, GEMM_SMEM>>>(
        Phi,  Plo,  P2hi, P2lo, P3hi, P3lo, 3,
        P2hi, P2lo, P2hi, P2lo, P4hi, P4lo, 4, out);
    // 4) slots 5,6,7
    diag3_kernel<<<2048, 256>>>(P2hi, P2lo, P3hi, P3lo, P4hi, P4lo, out);
}

// round 15
// speedup vs baseline: 1.1541x; 1.0068x over previous
#include <cuda_runtime.h>
#include <cuda_bf16.h>
#include <mma.h>
#include <cstdint>

using namespace nvcuda;

#define NN 256
#define MATS (256LL * 256 * 256)

// scratch (static __device__ arrays: allocation-free)
__device__ __nv_bfloat16 g_Phi[MATS], g_Plo[MATS];
__device__ __nv_bfloat16 g_P2hi[MATS], g_P2lo[MATS];
__device__ __nv_bfloat16 g_P3hi[MATS], g_P3lo[MATS];
__device__ __nv_bfloat16 g_P4hi[MATS], g_P4lo[MATS];

__device__ __forceinline__ uint32_t smem_u32(const void* p) {
    uint32_t a;
    asm("{ .reg .u64 t; cvta.to.shared.u64 t, %1; cvt.u32.u64 %0, t; }" : "=r"(a) : "l"(p));
    return a;
}
__device__ __forceinline__ void cpa16(uint32_t dst, const void* src) {
    asm volatile("cp.async.cg.shared.global [%0], [%1], 16;" :: "r"(dst), "l"(src));
}
__device__ __forceinline__ void cpa_commit() {
    asm volatile("cp.async.commit_group;" ::: "memory");
}
__device__ __forceinline__ float bf2f(__nv_bfloat16 v) { return __bfloat162float(v); }

// ---------------------------------------------------------------------------
// prep: threshold + row-normalize. Warp per row. Writes bf16 hi/lo of P +
// slots 0/1.
// ---------------------------------------------------------------------------
__global__ void __launch_bounds__(256) prep_kernel(const float* __restrict__ A,
                                                   __nv_bfloat16* __restrict__ Phi,
                                                   __nv_bfloat16* __restrict__ Plo,
                                                   float* __restrict__ out)
{
    int row = blockIdx.x * 8 + (threadIdx.x >> 5);
    int lane = threadIdx.x & 31;
    int n = row & 255;

    const float* arow = A + (size_t)row * NN + lane * 8;
    float4 v0 = *(const float4*)(arow);
    float4 v1 = *(const float4*)(arow + 4);
    float f[8] = {v0.x, v0.y, v0.z, v0.w, v1.x, v1.y, v1.z, v1.w};
    float s = 0.0f;
    #pragma unroll
    for (int q = 0; q < 8; q++) {
        f[q] = (f[q] > 0.3f) ? f[q] : 0.0f;
        s += f[q];
    }
    #pragma unroll
    for (int o = 16; o; o >>= 1) s += __shfl_xor_sync(0xffffffffu, s, o);
    float dinv = (s > 0.0f) ? (1.0f / s) : 0.0f;

    uint32_t hp[4], lp[4];
    float p[8];
    #pragma unroll
    for (int q = 0; q < 4; q++) {
        p[2*q]   = f[2*q]   * dinv;
        p[2*q+1] = f[2*q+1] * dinv;
        __nv_bfloat16 h0 = __float2bfloat16_rn(p[2*q]);
        __nv_bfloat16 h1 = __float2bfloat16_rn(p[2*q+1]);
        __nv_bfloat162 hh; hh.x = h0; hh.y = h1;
        hp[q] = *(uint32_t*)&hh;
        __nv_bfloat162 ll;
        ll.x = __float2bfloat16_rn(p[2*q]   - bf2f(h0));
        ll.y = __float2bfloat16_rn(p[2*q+1] - bf2f(h1));
        lp[q] = *(uint32_t*)&ll;
    }
    size_t idx = (size_t)row * NN + lane * 8;
    *(uint4*)(Phi + idx) = make_uint4(hp[0], hp[1], hp[2], hp[3]);
    *(uint4*)(Plo + idx) = make_uint4(lp[0], lp[1], lp[2], lp[3]);

    if (lane == (n >> 3)) out[(size_t)row * 8 + 1] = p[n & 7];
    if (lane == 0)        out[(size_t)row * 8 + 0] = 1.0f;
}

// ---------------------------------------------------------------------------
// WMMA bf16-split GEMM (R8-proven): C = X * Y, row-major [M,K]x[K,N].
// CTA: 256 thr / 8 warps, tile 128x128, warp tile 64x32, K-chunk 32,
// THREE-stage cp.async pipeline (depth 2), ONE sync per chunk (trailing
// barrier removed — redundant with 3 stages, see R15 analysis).
// 3 split products: XhYh + XhYl + XlYh.
// Epilogue: smem-staged C -> bf16 hi/lo + diag slot.
// blockIdx.z selects one of two problem descriptors (dual launch).
// ---------------------------------------------------------------------------
#define XLD 40
#define YLD 136
#define XARR_B (128 * XLD * 2)               // 10240
#define YARR_B (32 * YLD * 2)                // 8704
#define OFF_XL XARR_B
#define OFF_YH (2 * XARR_B)
#define OFF_YL (2 * XARR_B + YARR_B)
#define STAGE_B (2 * XARR_B + 2 * YARR_B)    // 37888
#define GEMM_SMEM (3 * STAGE_B)              // 113664 (2 CTA/SM)
#define CLD 132                              // epilogue stage ld; 128*132*4=67584 fits

__global__ void __launch_bounds__(256, 2)
gemm_wmma(const __nv_bfloat16* __restrict__ Xh0, const __nv_bfloat16* __restrict__ Xl0,
          const __nv_bfloat16* __restrict__ Yh0, const __nv_bfloat16* __restrict__ Yl0,
          __nv_bfloat16* __restrict__ Chi0, __nv_bfloat16* __restrict__ Clo0, int slot0,
          const __nv_bfloat16* __restrict__ Xh1, const __nv_bfloat16* __restrict__ Xl1,
          const __nv_bfloat16* __restrict__ Yh1, const __nv_bfloat16* __restrict__ Yl1,
          __nv_bfloat16* __restrict__ Chi1, __nv_bfloat16* __restrict__ Clo1, int slot1,
          float* __restrict__ out)
{
    const __nv_bfloat16* Xh = blockIdx.z ? Xh1 : Xh0;
    const __nv_bfloat16* Xl = blockIdx.z ? Xl1 : Xl0;
    const __nv_bfloat16* Yh = blockIdx.z ? Yh1 : Yh0;
    const __nv_bfloat16* Yl = blockIdx.z ? Yl1 : Yl0;
    __nv_bfloat16* Chi = blockIdx.z ? Chi1 : Chi0;
    __nv_bfloat16* Clo = blockIdx.z ? Clo1 : Clo0;
    int slot = blockIdx.z ? slot1 : slot0;

    int b = blockIdx.y;
    size_t base = (size_t)b << 16;
    Xh += base; Xl += base; Yh += base; Yl += base;
    Chi += base; Clo += base;
    int tileM = (blockIdx.x >> 1) << 7;
    int tileN = (blockIdx.x & 1) << 7;

    extern __shared__ __align__(128) char sm[];
    uint32_t smb = smem_u32(sm);

    int t = threadIdx.x;
    int w = t >> 5, wm = w & 1, wn = w >> 1;

    int xr = t >> 1, xq = t & 1;   // X: 128 rows x 2x32B
    int yr = t >> 4, yq = t & 15;  // Y: 32 rows x 16x16B

    wmma::fragment<wmma::accumulator, 16, 16, 16, float> acc[4][2];
    #pragma unroll
    for (int i = 0; i < 4; i++)
        #pragma unroll
        for (int j = 0; j < 2; j++) wmma::fill_fragment(acc[i][j], 0.0f);

    auto issue = [&](int kc, int s) {
        int k0 = kc << 5;
        uint32_t sb = smb + s * STAGE_B;
        {
            const __nv_bfloat16* gh = Xh + (size_t)(tileM + xr) * NN + k0 + xq * 16;
            const __nv_bfloat16* gl = Xl + (size_t)(tileM + xr) * NN + k0 + xq * 16;
            uint32_t d = sb + xr * (XLD * 2) + xq * 32;
            cpa16(d, gh);               cpa16(d + 16, gh + 8);
            cpa16(d + OFF_XL, gl);      cpa16(d + OFF_XL + 16, gl + 8);
        }
        {
            const __nv_bfloat16* gh = Yh + (size_t)(k0 + yr) * NN + tileN + yq * 8;
            const __nv_bfloat16* gl = Yl + (size_t)(k0 + yr) * NN + tileN + yq * 8;
            uint32_t d = sb + OFF_YH + yr * (YLD * 2) + yq * 16;
            cpa16(d, gh);               cpa16(d + 16 * (YLD * 2), gh + 16 * NN);
            cpa16(d + YARR_B, gl);      cpa16(d + YARR_B + 16 * (YLD * 2), gl + 16 * NN);
        }
        cpa_commit();
    };

    issue(0, 0);
    issue(1, 1);

    int scur = 0, sis = 2;
    #pragma unroll 1
    for (int kc = 0; kc < 8; kc++) {
        if (kc < 6) asm volatile("cp.async.wait_group 1;" ::: "memory");
        else        asm volatile("cp.async.wait_group 0;" ::: "memory");
        __syncthreads();
        if (kc < 6) issue(kc + 2, sis);

        const char* sb = sm + scur * STAGE_B;
        const __nv_bfloat16* bXh = (const __nv_bfloat16*)(sb);
        const __nv_bfloat16* bXl = (const __nv_bfloat16*)(sb + OFF_XL);
        const __nv_bfloat16* bYh = (const __nv_bfloat16*)(sb + OFF_YH);
        const __nv_bfloat16* bYl = (const __nv_bfloat16*)(sb + OFF_YL);

        #pragma unroll
        for (int kk = 0; kk < 2; kk++) {
            int ks = kk * 16;
            wmma::fragment<wmma::matrix_a, 16, 16, 16, __nv_bfloat16, wmma::row_major> ah[4], al[4];
            wmma::fragment<wmma::matrix_b, 16, 16, 16, __nv_bfloat16, wmma::row_major> bh[2], bl[2];
            #pragma unroll
            for (int i = 0; i < 4; i++) {
                wmma::load_matrix_sync(ah[i], bXh + (wm * 64 + i * 16) * XLD + ks, XLD);
                wmma::load_matrix_sync(al[i], bXl + (wm * 64 + i * 16) * XLD + ks, XLD);
            }
            #pragma unroll
            for (int j = 0; j < 2; j++) {
                wmma::load_matrix_sync(bh[j], bYh + ks * YLD + wn * 32 + j * 16, YLD);
                wmma::load_matrix_sync(bl[j], bYl + ks * YLD + wn * 32 + j * 16, YLD);
            }
            #pragma unroll
            for (int i = 0; i < 4; i++)
                #pragma unroll
                for (int j = 0; j < 2; j++) {
                    wmma::mma_sync(acc[i][j], ah[i], bh[j], acc[i][j]);
                    wmma::mma_sync(acc[i][j], ah[i], bl[j], acc[i][j]);
                    wmma::mma_sync(acc[i][j], al[i], bh[j], acc[i][j]);
                }
        }
        scur = (scur == 2) ? 0 : scur + 1;
        sis  = (sis  == 2) ? 0 : sis + 1;
        // NOTE: no trailing __syncthreads — the top-of-iteration barrier is
        // sufficient with a 3-stage ring (write target at kc is the stage
        // whose last reader finished before that barrier).
    }

    // epilogue: stage 128x128 fp32 tile in smem, emit bf16 hi/lo + diag slot
    __syncthreads();
    float* cs = (float*)sm;
    #pragma unroll
    for (int i = 0; i < 4; i++)
        #pragma unroll
        for (int j = 0; j < 2; j++)
            wmma::store_matrix_sync(cs + (wm * 64 + i * 16) * CLD + wn * 32 + j * 16,
                                    acc[i][j], CLD, wmma::mem_row_major);
    __syncthreads();

    if (tileM == tileN && t < 128)
        out[((size_t)(b << 8) + tileM + t) * 8 + slot] = cs[t * CLD + t];

    #pragma unroll
    for (int it = 0; it < 8; it++) {
        int idx = t + it * 256;
        int r = idx >> 4;
        int c = (idx & 15) << 3;
        const float* sp = cs + r * CLD + c;
        float f[8];
        #pragma unroll
        for (int q = 0; q < 8; q++) f[q] = sp[q];
        uint32_t hp[4], lp[4];
        #pragma unroll
        for (int q = 0; q < 4; q++) {
            __nv_bfloat16 h0 = __float2bfloat16_rn(f[2*q]);
            __nv_bfloat16 h1 = __float2bfloat16_rn(f[2*q+1]);
            __nv_bfloat162 hh; hh.x = h0; hh.y = h1;
            hp[q] = *(uint32_t*)&hh;
            __nv_bfloat162 ll;
            ll.x = __float2bfloat16_rn(f[2*q]   - bf2f(h0));
            ll.y = __float2bfloat16_rn(f[2*q+1] - bf2f(h1));
            lp[q] = *(uint32_t*)&ll;
        }
        *(uint4*)(Chi + (size_t)(tileM + r) * NN + tileN + c) = make_uint4(hp[0], hp[1], hp[2], hp[3]);
        *(uint4*)(Clo + (size_t)(tileM + r) * NN + tileN + c) = make_uint4(lp[0], lp[1], lp[2], lp[3]);
    }
}

// ---------------------------------------------------------------------------
// diag3 (R8-proven): d5 = <P2[i,:], P3[:,i]>, d6 = <P3[i,:], P3[:,i]>,
// d7 = <P3[i,:], P4[:,i]>. Columns staged through smem (coalesced),
// all inputs bf16 hi/lo reconstructed. 8.4 KB smem, 32 regs, occ ~85%.
// ---------------------------------------------------------------------------
__global__ void __launch_bounds__(256) diag3_kernel(const __nv_bfloat16* __restrict__ P2h,
                                                    const __nv_bfloat16* __restrict__ P2l,
                                                    const __nv_bfloat16* __restrict__ P3h,
                                                    const __nv_bfloat16* __restrict__ P3l,
                                                    const __nv_bfloat16* __restrict__ P4h,
                                                    const __nv_bfloat16* __restrict__ P4l,
                                                    float* __restrict__ out)
{
    __shared__ float c3[32][33], c4[32][33];
    int b = blockIdx.x >> 3;
    int i0 = (blockIdx.x & 7) << 5;
    size_t base = (size_t)b << 16;
    int t = threadIdx.x;
    int il = t >> 3, jq = t & 7;
    int lc = t & 31, lr = t >> 5;

    const __nv_bfloat16* r2h = P2h + base + (size_t)(i0 + il) * NN;
    const __nv_bfloat16* r2l = P2l + base + (size_t)(i0 + il) * NN;
    const __nv_bfloat16* r3h = P3h + base + (size_t)(i0 + il) * NN;
    const __nv_bfloat16* r3l = P3l + base + (size_t)(i0 + il) * NN;

    float a5 = 0.f, a6 = 0.f, a7 = 0.f;
    #pragma unroll 1
    for (int jt = 0; jt < 8; jt++) {
        int j0 = jt << 5;
        #pragma unroll
        for (int qq = 0; qq < 4; qq++) {
            int jl = lr + qq * 8;
            size_t src = base + (size_t)(j0 + jl) * NN + i0 + lc;
            c3[jl][lc] = bf2f(P3h[src]) + bf2f(P3l[src]);
            c4[jl][lc] = bf2f(P4h[src]) + bf2f(P4l[src]);
        }
        __syncthreads();

        uint2 u2h = *(const uint2*)(r2h + j0 + jq * 4);
        uint2 u2l = *(const uint2*)(r2l + j0 + jq * 4);
        uint2 u3h = *(const uint2*)(r3h + j0 + jq * 4);
        uint2 u3l = *(const uint2*)(r3l + j0 + jq * 4);
        float x2[4], x3[4];
        {
            __nv_bfloat162 h0 = *(__nv_bfloat162*)&u2h.x, h1 = *(__nv_bfloat162*)&u2h.y;
            __nv_bfloat162 l0 = *(__nv_bfloat162*)&u2l.x, l1 = *(__nv_bfloat162*)&u2l.y;
            x2[0] = bf2f(h0.x) + bf2f(l0.x); x2[1] = bf2f(h0.y) + bf2f(l0.y);
            x2[2] = bf2f(h1.x) + bf2f(l1.x); x2[3] = bf2f(h1.y) + bf2f(l1.y);
        }
        {
            __nv_bfloat162 h0 = *(__nv_bfloat162*)&u3h.x, h1 = *(__nv_bfloat162*)&u3h.y;
            __nv_bfloat162 l0 = *(__nv_bfloat162*)&u3l.x, l1 = *(__nv_bfloat162*)&u3l.y;
            x3[0] = bf2f(h0.x) + bf2f(l0.x); x3[1] = bf2f(h0.y) + bf2f(l0.y);
            x3[2] = bf2f(h1.x) + bf2f(l1.x); x3[3] = bf2f(h1.y) + bf2f(l1.y);
        }
        int jb = jq * 4;
        #pragma unroll
        for (int k = 0; k < 4; k++) {
            float cc3 = c3[jb + k][il];
            float cc4 = c4[jb + k][il];
            a5 = fmaf(x2[k], cc3, a5);
            a6 = fmaf(x3[k], cc3, a6);
            a7 = fmaf(x3[k], cc4, a7);
        }
        __syncthreads();
    }
    #pragma unroll
    for (int o = 4; o; o >>= 1) {
        a5 += __shfl_down_sync(0xffffffffu, a5, o);
        a6 += __shfl_down_sync(0xffffffffu, a6, o);
        a7 += __shfl_down_sync(0xffffffffu, a7, o);
    }
    if (jq == 0) {
        size_t o = ((size_t)(b << 8) + i0 + il) * 8;
        out[o + 5] = a5;
        out[o + 6] = a6;
        out[o + 7] = a7;
    }
}

// ---------------------------------------------------------------------------
extern "C" void kernel_launch(void* const* d_in, const int* in_sizes, int n_in,
                              void* d_out, int out_size)
{
    const float* A = (const float*)d_in[0];
    float* out = (float*)d_out;

    __nv_bfloat16 *Phi, *Plo, *P2hi, *P2lo, *P3hi, *P3lo, *P4hi, *P4lo;
    cudaGetSymbolAddress((void**)&Phi,  g_Phi);
    cudaGetSymbolAddress((void**)&Plo,  g_Plo);
    cudaGetSymbolAddress((void**)&P2hi, g_P2hi);
    cudaGetSymbolAddress((void**)&P2lo, g_P2lo);
    cudaGetSymbolAddress((void**)&P3hi, g_P3hi);
    cudaGetSymbolAddress((void**)&P3lo, g_P3lo);
    cudaGetSymbolAddress((void**)&P4hi, g_P4hi);
    cudaGetSymbolAddress((void**)&P4lo, g_P4lo);

    cudaFuncSetAttribute(gemm_wmma, cudaFuncAttributeMaxDynamicSharedMemorySize, GEMM_SMEM);

    // 1) P (bf16 hi/lo) + slots 0,1
    prep_kernel<<<8192, 256>>>(A, Phi, Plo, out);
    // 2) P2 = P * P (bf16 hi/lo) + slot 2
    gemm_wmma<<<dim3(4, 256, 1), 256, GEMM_SMEM>>>(
        Phi, Plo, Phi, Plo, P2hi, P2lo, 2,
        Phi, Plo, Phi, Plo, P2hi, P2lo, 2, out);
    // 3) dual launch: P3 = P*P2 (slot 3) and P4 = P2*P2 (slot 4)
    gemm_wmma<<<dim3(4, 256, 2), 256, GEMM_SMEM>>>(
        Phi,  Plo,  P2hi, P2lo, P3hi, P3lo, 3,
        P2hi, P2lo, P2hi, P2lo, P4hi, P4lo, 4, out);
    // 4) slots 5,6,7
    diag3_kernel<<<2048, 256>>>(P2hi, P2lo, P3hi, P3lo, P4hi, P4lo, out);
}

// round 16
// speedup vs baseline: 1.2198x; 1.0570x over previous
#include <cuda_runtime.h>
#include <cuda_bf16.h>
#include <mma.h>
#include <cstdint>

using namespace nvcuda;

#define NN 256
#define MATS (256LL * 256 * 256)

// scratch (static __device__ arrays: allocation-free)
__device__ __nv_bfloat16 g_Phi[MATS], g_Plo[MATS];
__device__ __nv_bfloat16 g_P2hi[MATS], g_P2lo[MATS];
__device__ __nv_bfloat16 g_P3hi[MATS], g_P3lo[MATS];
__device__ __nv_bfloat16 g_P4hi[MATS], g_P4lo[MATS];

__device__ __forceinline__ uint32_t smem_u32(const void* p) {
    uint32_t a;
    asm("{ .reg .u64 t; cvta.to.shared.u64 t, %1; cvt.u32.u64 %0, t; }" : "=r"(a) : "l"(p));
    return a;
}
__device__ __forceinline__ void cpa16(uint32_t dst, const void* src) {
    asm volatile("cp.async.cg.shared.global [%0], [%1], 16;" :: "r"(dst), "l"(src));
}
__device__ __forceinline__ void cpa_commit() {
    asm volatile("cp.async.commit_group;" ::: "memory");
}
__device__ __forceinline__ float bf2f(__nv_bfloat16 v) { return __bfloat162float(v); }

// ---------------------------------------------------------------------------
// prep: threshold + row-normalize. Warp per row. Writes bf16 hi/lo of P +
// slots 0/1.
// ---------------------------------------------------------------------------
__global__ void __launch_bounds__(256) prep_kernel(const float* __restrict__ A,
                                                   __nv_bfloat16* __restrict__ Phi,
                                                   __nv_bfloat16* __restrict__ Plo,
                                                   float* __restrict__ out)
{
    int row = blockIdx.x * 8 + (threadIdx.x >> 5);
    int lane = threadIdx.x & 31;
    int n = row & 255;

    const float* arow = A + (size_t)row * NN + lane * 8;
    float4 v0 = *(const float4*)(arow);
    float4 v1 = *(const float4*)(arow + 4);
    float f[8] = {v0.x, v0.y, v0.z, v0.w, v1.x, v1.y, v1.z, v1.w};
    float s = 0.0f;
    #pragma unroll
    for (int q = 0; q < 8; q++) {
        f[q] = (f[q] > 0.3f) ? f[q] : 0.0f;
        s += f[q];
    }
    #pragma unroll
    for (int o = 16; o; o >>= 1) s += __shfl_xor_sync(0xffffffffu, s, o);
    float dinv = (s > 0.0f) ? (1.0f / s) : 0.0f;

    uint32_t hp[4], lp[4];
    float p[8];
    #pragma unroll
    for (int q = 0; q < 4; q++) {
        p[2*q]   = f[2*q]   * dinv;
        p[2*q+1] = f[2*q+1] * dinv;
        __nv_bfloat16 h0 = __float2bfloat16_rn(p[2*q]);
        __nv_bfloat16 h1 = __float2bfloat16_rn(p[2*q+1]);
        __nv_bfloat162 hh; hh.x = h0; hh.y = h1;
        hp[q] = *(uint32_t*)&hh;
        __nv_bfloat162 ll;
        ll.x = __float2bfloat16_rn(p[2*q]   - bf2f(h0));
        ll.y = __float2bfloat16_rn(p[2*q+1] - bf2f(h1));
        lp[q] = *(uint32_t*)&ll;
    }
    size_t idx = (size_t)row * NN + lane * 8;
    *(uint4*)(Phi + idx) = make_uint4(hp[0], hp[1], hp[2], hp[3]);
    *(uint4*)(Plo + idx) = make_uint4(lp[0], lp[1], lp[2], lp[3]);

    if (lane == (n >> 3)) out[(size_t)row * 8 + 1] = p[n & 7];
    if (lane == 0)        out[(size_t)row * 8 + 0] = 1.0f;
}

// ---------------------------------------------------------------------------
// WMMA bf16-split GEMM (R8 byte-exact): C = X * Y, row-major [M,K]x[K,N].
// CTA: 256 thr / 8 warps, tile 128x128, warp tile 64x32, K-chunk 32,
// THREE-stage cp.async pipeline (depth 2), sync at top AND bottom of chunk
// (trailing barrier is load-bearing: keeps loader bursts convergent, R15).
// 3 split products: XhYh + XhYl + XlYh.
// Epilogue: smem-staged C -> bf16 hi/lo + diag slot.
// blockIdx.z selects one of two problem descriptors (dual launch).
// ---------------------------------------------------------------------------
#define XLD 40
#define YLD 136
#define XARR_B (128 * XLD * 2)               // 10240
#define YARR_B (32 * YLD * 2)                // 8704
#define OFF_XL XARR_B
#define OFF_YH (2 * XARR_B)
#define OFF_YL (2 * XARR_B + YARR_B)
#define STAGE_B (2 * XARR_B + 2 * YARR_B)    // 37888
#define GEMM_SMEM (3 * STAGE_B)              // 113664 (2 CTA/SM)
#define CLD 132                              // epilogue stage ld; 128*132*4=67584 fits

__global__ void __launch_bounds__(256, 2)
gemm_wmma(const __nv_bfloat16* __restrict__ Xh0, const __nv_bfloat16* __restrict__ Xl0,
          const __nv_bfloat16* __restrict__ Yh0, const __nv_bfloat16* __restrict__ Yl0,
          __nv_bfloat16* __restrict__ Chi0, __nv_bfloat16* __restrict__ Clo0, int slot0,
          const __nv_bfloat16* __restrict__ Xh1, const __nv_bfloat16* __restrict__ Xl1,
          const __nv_bfloat16* __restrict__ Yh1, const __nv_bfloat16* __restrict__ Yl1,
          __nv_bfloat16* __restrict__ Chi1, __nv_bfloat16* __restrict__ Clo1, int slot1,
          float* __restrict__ out)
{
    const __nv_bfloat16* Xh = blockIdx.z ? Xh1 : Xh0;
    const __nv_bfloat16* Xl = blockIdx.z ? Xl1 : Xl0;
    const __nv_bfloat16* Yh = blockIdx.z ? Yh1 : Yh0;
    const __nv_bfloat16* Yl = blockIdx.z ? Yl1 : Yl0;
    __nv_bfloat16* Chi = blockIdx.z ? Chi1 : Chi0;
    __nv_bfloat16* Clo = blockIdx.z ? Clo1 : Clo0;
    int slot = blockIdx.z ? slot1 : slot0;

    int b = blockIdx.y;
    size_t base = (size_t)b << 16;
    Xh += base; Xl += base; Yh += base; Yl += base;
    Chi += base; Clo += base;
    int tileM = (blockIdx.x >> 1) << 7;
    int tileN = (blockIdx.x & 1) << 7;

    extern __shared__ __align__(128) char sm[];
    uint32_t smb = smem_u32(sm);

    int t = threadIdx.x;
    int w = t >> 5, wm = w & 1, wn = w >> 1;

    int xr = t >> 1, xq = t & 1;   // X: 128 rows x 2x32B
    int yr = t >> 4, yq = t & 15;  // Y: 32 rows x 16x16B

    wmma::fragment<wmma::accumulator, 16, 16, 16, float> acc[4][2];
    #pragma unroll
    for (int i = 0; i < 4; i++)
        #pragma unroll
        for (int j = 0; j < 2; j++) wmma::fill_fragment(acc[i][j], 0.0f);

    auto issue = [&](int kc, int s) {
        int k0 = kc << 5;
        uint32_t sb = smb + s * STAGE_B;
        {
            const __nv_bfloat16* gh = Xh + (size_t)(tileM + xr) * NN + k0 + xq * 16;
            const __nv_bfloat16* gl = Xl + (size_t)(tileM + xr) * NN + k0 + xq * 16;
            uint32_t d = sb + xr * (XLD * 2) + xq * 32;
            cpa16(d, gh);               cpa16(d + 16, gh + 8);
            cpa16(d + OFF_XL, gl);      cpa16(d + OFF_XL + 16, gl + 8);
        }
        {
            const __nv_bfloat16* gh = Yh + (size_t)(k0 + yr) * NN + tileN + yq * 8;
            const __nv_bfloat16* gl = Yl + (size_t)(k0 + yr) * NN + tileN + yq * 8;
            uint32_t d = sb + OFF_YH + yr * (YLD * 2) + yq * 16;
            cpa16(d, gh);               cpa16(d + 16 * (YLD * 2), gh + 16 * NN);
            cpa16(d + YARR_B, gl);      cpa16(d + YARR_B + 16 * (YLD * 2), gl + 16 * NN);
        }
        cpa_commit();
    };

    issue(0, 0);
    issue(1, 1);

    int scur = 0, sis = 2;
    #pragma unroll 1
    for (int kc = 0; kc < 8; kc++) {
        if (kc < 6) asm volatile("cp.async.wait_group 1;" ::: "memory");
        else        asm volatile("cp.async.wait_group 0;" ::: "memory");
        __syncthreads();
        if (kc < 6) issue(kc + 2, sis);

        const char* sb = sm + scur * STAGE_B;
        const __nv_bfloat16* bXh = (const __nv_bfloat16*)(sb);
        const __nv_bfloat16* bXl = (const __nv_bfloat16*)(sb + OFF_XL);
        const __nv_bfloat16* bYh = (const __nv_bfloat16*)(sb + OFF_YH);
        const __nv_bfloat16* bYl = (const __nv_bfloat16*)(sb + OFF_YL);

        #pragma unroll
        for (int kk = 0; kk < 2; kk++) {
            int ks = kk * 16;
            wmma::fragment<wmma::matrix_a, 16, 16, 16, __nv_bfloat16, wmma::row_major> ah[4], al[4];
            wmma::fragment<wmma::matrix_b, 16, 16, 16, __nv_bfloat16, wmma::row_major> bh[2], bl[2];
            #pragma unroll
            for (int i = 0; i < 4; i++) {
                wmma::load_matrix_sync(ah[i], bXh + (wm * 64 + i * 16) * XLD + ks, XLD);
                wmma::load_matrix_sync(al[i], bXl + (wm * 64 + i * 16) * XLD + ks, XLD);
            }
            #pragma unroll
            for (int j = 0; j < 2; j++) {
                wmma::load_matrix_sync(bh[j], bYh + ks * YLD + wn * 32 + j * 16, YLD);
                wmma::load_matrix_sync(bl[j], bYl + ks * YLD + wn * 32 + j * 16, YLD);
            }
            #pragma unroll
            for (int i = 0; i < 4; i++)
                #pragma unroll
                for (int j = 0; j < 2; j++) {
                    wmma::mma_sync(acc[i][j], ah[i], bh[j], acc[i][j]);
                    wmma::mma_sync(acc[i][j], ah[i], bl[j], acc[i][j]);
                    wmma::mma_sync(acc[i][j], al[i], bh[j], acc[i][j]);
                }
        }
        scur = (scur == 2) ? 0 : scur + 1;
        sis  = (sis  == 2) ? 0 : sis + 1;
        __syncthreads();
    }

    // epilogue: stage 128x128 fp32 tile in smem, emit bf16 hi/lo + diag slot
    float* cs = (float*)sm;
    #pragma unroll
    for (int i = 0; i < 4; i++)
        #pragma unroll
        for (int j = 0; j < 2; j++)
            wmma::store_matrix_sync(cs + (wm * 64 + i * 16) * CLD + wn * 32 + j * 16,
                                    acc[i][j], CLD, wmma::mem_row_major);
    __syncthreads();

    if (tileM == tileN && t < 128)
        out[((size_t)(b << 8) + tileM + t) * 8 + slot] = cs[t * CLD + t];

    #pragma unroll
    for (int it = 0; it < 8; it++) {
        int idx = t + it * 256;
        int r = idx >> 4;
        int c = (idx & 15) << 3;
        const float* sp = cs + r * CLD + c;
        float f[8];
        #pragma unroll
        for (int q = 0; q < 8; q++) f[q] = sp[q];
        uint32_t hp[4], lp[4];
        #pragma unroll
        for (int q = 0; q < 4; q++) {
            __nv_bfloat16 h0 = __float2bfloat16_rn(f[2*q]);
            __nv_bfloat16 h1 = __float2bfloat16_rn(f[2*q+1]);
            __nv_bfloat162 hh; hh.x = h0; hh.y = h1;
            hp[q] = *(uint32_t*)&hh;
            __nv_bfloat162 ll;
            ll.x = __float2bfloat16_rn(f[2*q]   - bf2f(h0));
            ll.y = __float2bfloat16_rn(f[2*q+1] - bf2f(h1));
            lp[q] = *(uint32_t*)&ll;
        }
        *(uint4*)(Chi + (size_t)(tileM + r) * NN + tileN + c) = make_uint4(hp[0], hp[1], hp[2], hp[3]);
        *(uint4*)(Clo + (size_t)(tileM + r) * NN + tileN + c) = make_uint4(lp[0], lp[1], lp[2], lp[3]);
    }
}

// ---------------------------------------------------------------------------
// diag3 v4: all three dots share ONE staged P3-column tile (powers commute:
// d7 = diag(P4*P3) = <P4[i,:], P3[:,i]>).
//   d5 = <P2[i,:], P3[:,i]>,  d6 = <P3[i,:], P3[:,i]>,  d7 = <P4[i,:], P3[:,i]>
// Same block/thread structure as the proven R8 version; c4 staging deleted
// (smem 8.4->4.2 KB, global loads per j-tile 20->14, smem stores halved).
// ---------------------------------------------------------------------------
__global__ void __launch_bounds__(256) diag3_kernel(const __nv_bfloat16* __restrict__ P2h,
                                                    const __nv_bfloat16* __restrict__ P2l,
                                                    const __nv_bfloat16* __restrict__ P3h,
                                                    const __nv_bfloat16* __restrict__ P3l,
                                                    const __nv_bfloat16* __restrict__ P4h,
                                                    const __nv_bfloat16* __restrict__ P4l,
                                                    float* __restrict__ out)
{
    __shared__ float c3[32][33];
    int b = blockIdx.x >> 3;
    int i0 = (blockIdx.x & 7) << 5;
    size_t base = (size_t)b << 16;
    int t = threadIdx.x;
    int il = t >> 3, jq = t & 7;
    int lc = t & 31, lr = t >> 5;

    const __nv_bfloat16* r2h = P2h + base + (size_t)(i0 + il) * NN;
    const __nv_bfloat16* r2l = P2l + base + (size_t)(i0 + il) * NN;
    const __nv_bfloat16* r3h = P3h + base + (size_t)(i0 + il) * NN;
    const __nv_bfloat16* r3l = P3l + base + (size_t)(i0 + il) * NN;
    const __nv_bfloat16* r4h = P4h + base + (size_t)(i0 + il) * NN;
    const __nv_bfloat16* r4l = P4l + base + (size_t)(i0 + il) * NN;

    float a5 = 0.f, a6 = 0.f, a7 = 0.f;
    #pragma unroll 1
    for (int jt = 0; jt < 8; jt++) {
        int j0 = jt << 5;
        #pragma unroll
        for (int qq = 0; qq < 4; qq++) {
            int jl = lr + qq * 8;
            size_t src = base + (size_t)(j0 + jl) * NN + i0 + lc;
            c3[jl][lc] = bf2f(P3h[src]) + bf2f(P3l[src]);
        }
        __syncthreads();

        uint2 u2h = *(const uint2*)(r2h + j0 + jq * 4);
        uint2 u2l = *(const uint2*)(r2l + j0 + jq * 4);
        uint2 u3h = *(const uint2*)(r3h + j0 + jq * 4);
        uint2 u3l = *(const uint2*)(r3l + j0 + jq * 4);
        uint2 u4h = *(const uint2*)(r4h + j0 + jq * 4);
        uint2 u4l = *(const uint2*)(r4l + j0 + jq * 4);
        float x2[4], x3[4], x4[4];
        {
            __nv_bfloat162 h0 = *(__nv_bfloat162*)&u2h.x, h1 = *(__nv_bfloat162*)&u2h.y;
            __nv_bfloat162 l0 = *(__nv_bfloat162*)&u2l.x, l1 = *(__nv_bfloat162*)&u2l.y;
            x2[0] = bf2f(h0.x) + bf2f(l0.x); x2[1] = bf2f(h0.y) + bf2f(l0.y);
            x2[2] = bf2f(h1.x) + bf2f(l1.x); x2[3] = bf2f(h1.y) + bf2f(l1.y);
        }
        {
            __nv_bfloat162 h0 = *(__nv_bfloat162*)&u3h.x, h1 = *(__nv_bfloat162*)&u3h.y;
            __nv_bfloat162 l0 = *(__nv_bfloat162*)&u3l.x, l1 = *(__nv_bfloat162*)&u3l.y;
            x3[0] = bf2f(h0.x) + bf2f(l0.x); x3[1] = bf2f(h0.y) + bf2f(l0.y);
            x3[2] = bf2f(h1.x) + bf2f(l1.x); x3[3] = bf2f(h1.y) + bf2f(l1.y);
        }
        {
            __nv_bfloat162 h0 = *(__nv_bfloat162*)&u4h.x, h1 = *(__nv_bfloat162*)&u4h.y;
            __nv_bfloat162 l0 = *(__nv_bfloat162*)&u4l.x, l1 = *(__nv_bfloat162*)&u4l.y;
            x4[0] = bf2f(h0.x) + bf2f(l0.x); x4[1] = bf2f(h0.y) + bf2f(l0.y);
            x4[2] = bf2f(h1.x) + bf2f(l1.x); x4[3] = bf2f(h1.y) + bf2f(l1.y);
        }
        int jb = jq * 4;
        #pragma unroll
        for (int k = 0; k < 4; k++) {
            float cc3 = c3[jb + k][il];
            a5 = fmaf(x2[k], cc3, a5);
            a6 = fmaf(x3[k], cc3, a6);
            a7 = fmaf(x4[k], cc3, a7);
        }
        __syncthreads();
    }
    #pragma unroll
    for (int o = 4; o; o >>= 1) {
        a5 += __shfl_down_sync(0xffffffffu, a5, o);
        a6 += __shfl_down_sync(0xffffffffu, a6, o);
        a7 += __shfl_down_sync(0xffffffffu, a7, o);
    }
    if (jq == 0) {
        size_t o = ((size_t)(b << 8) + i0 + il) * 8;
        out[o + 5] = a5;
        out[o + 6] = a6;
        out[o + 7] = a7;
    }
}

// ---------------------------------------------------------------------------
extern "C" void kernel_launch(void* const* d_in, const int* in_sizes, int n_in,
                              void* d_out, int out_size)
{
    const float* A = (const float*)d_in[0];
    float* out = (float*)d_out;

    __nv_bfloat16 *Phi, *Plo, *P2hi, *P2lo, *P3hi, *P3lo, *P4hi, *P4lo;
    cudaGetSymbolAddress((void**)&Phi,  g_Phi);
    cudaGetSymbolAddress((void**)&Plo,  g_Plo);
    cudaGetSymbolAddress((void**)&P2hi, g_P2hi);
    cudaGetSymbolAddress((void**)&P2lo, g_P2lo);
    cudaGetSymbolAddress((void**)&P3hi, g_P3hi);
    cudaGetSymbolAddress((void**)&P3lo, g_P3lo);
    cudaGetSymbolAddress((void**)&P4hi, g_P4hi);
    cudaGetSymbolAddress((void**)&P4lo, g_P4lo);

    cudaFuncSetAttribute(gemm_wmma, cudaFuncAttributeMaxDynamicSharedMemorySize, GEMM_SMEM);

    // 1) P (bf16 hi/lo) + slots 0,1
    prep_kernel<<<8192, 256>>>(A, Phi, Plo, out);
    // 2) P2 = P * P (bf16 hi/lo) + slot 2
    gemm_wmma<<<dim3(4, 256, 1), 256, GEMM_SMEM>>>(
        Phi, Plo, Phi, Plo, P2hi, P2lo, 2,
        Phi, Plo, Phi, Plo, P2hi, P2lo, 2, out);
    // 3) dual launch: P3 = P*P2 (slot 3) and P4 = P2*P2 (slot 4)
    gemm_wmma<<<dim3(4, 256, 2), 256, GEMM_SMEM>>>(
        Phi,  Plo,  P2hi, P2lo, P3hi, P3lo, 3,
        P2hi, P2lo, P2hi, P2lo, P4hi, P4lo, 4, out);
    // 4) slots 5,6,7
    diag3_kernel<<<2048, 256>>>(P2hi, P2lo, P3hi, P3lo, P4hi, P4lo, out);
}